// round 3
// baseline (speedup 1.0000x reference)
#include <cuda_runtime.h>
#include <cfloat>

// Fixed problem shape: img_features (1, 128, 224, 224) fp32, points (N,3), N<=1M.
#define C_CH   128
#define IMG    224
#define NPIX   (IMG * IMG)          // 50176
#define MAXPTS (1 << 20)

// Scratch (static device globals — no allocation at runtime).
__device__ float2 g_xy[MAXPTS];                 // transformed (x,y) per point, 8 MB
__device__ float  g_fmapT[NPIX * C_CH];         // feature map transposed to (x,y,c), 25.7 MB
__device__ int    g_minx, g_maxx, g_miny, g_maxy;   // ordered-int encoded float min/max

// Monotonic float<->int encoding for atomic min/max on floats.
__device__ __forceinline__ int f2oi(float f) {
    int i = __float_as_int(f);
    return (i >= 0) ? i : (i ^ 0x7fffffff);
}
__device__ __forceinline__ float oi2f(int i) {
    return __int_as_float((i >= 0) ? i : (i ^ 0x7fffffff));
}

__global__ void init_minmax_kernel() {
    g_minx = 0x7fffffff;            // +inf ordered
    g_miny = 0x7fffffff;
    g_maxx = 0x80000000;            // -inf ordered
    g_maxy = 0x80000000;
}

// Pass 1: p = points @ R + T (x,y only), stash, and global min/max reduce.
// Rounding pinned to XLA's loop emitter (NO fp contraction):
//   x = ((rn(p0*r0) + rn(p1*r3)) + rn(p2*r6)) + T   — every op individually rounded.
__global__ void transform_kernel(const float* __restrict__ pts,
                                 const float* __restrict__ Rm,
                                 const float* __restrict__ Tv,
                                 int n) {
    int i = blockIdx.x * blockDim.x + threadIdx.x;

    float lminx =  FLT_MAX, lmaxx = -FLT_MAX;
    float lminy =  FLT_MAX, lmaxy = -FLT_MAX;

    if (i < n) {
        float p0 = pts[3 * i + 0];
        float p1 = pts[3 * i + 1];
        float p2 = pts[3 * i + 2];
        float x = __fadd_rn(
                      __fadd_rn(
                          __fadd_rn(__fmul_rn(p0, Rm[0]), __fmul_rn(p1, Rm[3])),
                          __fmul_rn(p2, Rm[6])),
                      Tv[0]);
        float y = __fadd_rn(
                      __fadd_rn(
                          __fadd_rn(__fmul_rn(p0, Rm[1]), __fmul_rn(p1, Rm[4])),
                          __fmul_rn(p2, Rm[7])),
                      Tv[1]);
        g_xy[i] = make_float2(x, y);
        lminx = x; lmaxx = x;
        lminy = y; lmaxy = y;
    }

    // warp reduce
    #pragma unroll
    for (int o = 16; o > 0; o >>= 1) {
        lminx = fminf(lminx, __shfl_xor_sync(0xffffffffu, lminx, o));
        lmaxx = fmaxf(lmaxx, __shfl_xor_sync(0xffffffffu, lmaxx, o));
        lminy = fminf(lminy, __shfl_xor_sync(0xffffffffu, lminy, o));
        lmaxy = fmaxf(lmaxy, __shfl_xor_sync(0xffffffffu, lmaxy, o));
    }

    __shared__ float s0[8], s1[8], s2[8], s3[8];
    int wid  = threadIdx.x >> 5;
    int lane = threadIdx.x & 31;
    if (lane == 0) { s0[wid] = lminx; s1[wid] = lmaxx; s2[wid] = lminy; s3[wid] = lmaxy; }
    __syncthreads();

    if (threadIdx.x == 0) {
        float a = s0[0], b = s1[0], c = s2[0], d = s3[0];
        #pragma unroll
        for (int k = 1; k < 8; k++) {
            a = fminf(a, s0[k]); b = fmaxf(b, s1[k]);
            c = fminf(c, s2[k]); d = fmaxf(d, s3[k]);
        }
        atomicMin(&g_minx, f2oi(a));
        atomicMax(&g_maxx, f2oi(b));
        atomicMin(&g_miny, f2oi(c));
        atomicMax(&g_maxy, f2oi(d));
    }
}

// Pass 2: transpose feature map (C, P) -> (P, C) with P = x*224 + y.
// C=128 and P=50176 are exact multiples of 32 — no bounds checks.
__global__ void transpose_kernel(const float* __restrict__ A) {
    __shared__ float tile[32][33];
    int p0 = blockIdx.x * 32;
    int c0 = blockIdx.y * 32;

    #pragma unroll
    for (int dy = 0; dy < 32; dy += 8)
        tile[threadIdx.y + dy][threadIdx.x] =
            A[(size_t)(c0 + threadIdx.y + dy) * NPIX + (p0 + threadIdx.x)];
    __syncthreads();

    #pragma unroll
    for (int dy = 0; dy < 32; dy += 8)
        g_fmapT[(size_t)(p0 + threadIdx.y + dy) * C_CH + (c0 + threadIdx.x)] =
            tile[threadIdx.x][threadIdx.y + dy];
}

// Pass 3: one warp per point; lane handles 4 channels via float4.
// Feature rows in the transposed map are 128 floats = 32 float4 — fully coalesced.
__global__ void gather_kernel(float* __restrict__ out, int n) {
    int gtid = blockIdx.x * blockDim.x + threadIdx.x;
    int pi   = gtid >> 5;
    int lane = gtid & 31;
    if (pi >= n) return;

    float minx = oi2f(g_minx), maxx = oi2f(g_maxx);
    float miny = oi2f(g_miny), maxy = oi2f(g_maxy);
    // IEEE division — approximate-reciprocal divide flips floor/ceil bins.
    float sx = __fdiv_rn(223.99f, __fsub_rn(maxx, minx));
    float sy = __fdiv_rn(223.99f, __fsub_rn(maxy, miny));

    float2 xy = g_xy[pi];
    float xv = __fmul_rn(__fsub_rn(xy.x, minx), sx);
    float yv = __fmul_rn(__fsub_rn(xy.y, miny), sy);

    int x1 = (int)floorf(xv);
    int x2 = min((int)ceilf(xv), IMG - 1);
    int y1 = (int)floorf(yv);
    int y2 = min((int)ceilf(yv), IMG - 1);

    float x1f = (float)x1, x2f = (float)x2;
    float y1f = (float)y1, y2f = (float)y2;
    float w11 = __fmul_rn(__fsub_rn(x2f, xv), __fsub_rn(y2f, yv));
    float w12 = __fmul_rn(__fsub_rn(x2f, xv), __fsub_rn(yv, y1f));
    float w21 = __fmul_rn(__fsub_rn(xv, x1f), __fsub_rn(y2f, yv));
    float w22 = __fmul_rn(__fsub_rn(xv, x1f), __fsub_rn(yv, y1f));

    const float4* f = (const float4*)g_fmapT;
    int r1 = x1 * IMG, r2 = x2 * IMG;
    float4 q11 = f[(size_t)(r1 + y1) * 32 + lane];
    float4 q12 = f[(size_t)(r1 + y2) * 32 + lane];
    float4 q21 = f[(size_t)(r2 + y1) * 32 + lane];
    float4 q22 = f[(size_t)(r2 + y2) * 32 + lane];

    // reference order, no contraction: ((Q11*w11 + Q21*w21) + Q12*w12) + Q22*w22
    float4 o;
    o.x = __fadd_rn(__fadd_rn(__fadd_rn(__fmul_rn(q11.x, w11), __fmul_rn(q21.x, w21)),
                              __fmul_rn(q12.x, w12)), __fmul_rn(q22.x, w22));
    o.y = __fadd_rn(__fadd_rn(__fadd_rn(__fmul_rn(q11.y, w11), __fmul_rn(q21.y, w21)),
                              __fmul_rn(q12.y, w12)), __fmul_rn(q22.y, w22));
    o.z = __fadd_rn(__fadd_rn(__fadd_rn(__fmul_rn(q11.z, w11), __fmul_rn(q21.z, w21)),
                              __fmul_rn(q12.z, w12)), __fmul_rn(q22.z, w22));
    o.w = __fadd_rn(__fadd_rn(__fadd_rn(__fmul_rn(q11.w, w11), __fmul_rn(q21.w, w21)),
                              __fmul_rn(q12.w, w12)), __fmul_rn(q22.w, w22));

    ((float4*)out)[(size_t)pi * 32 + lane] = o;
}

extern "C" void kernel_launch(void* const* d_in, const int* in_sizes, int n_in,
                              void* d_out, int out_size) {
    const float* img = (const float*)d_in[0];   // (1, 128, 224, 224)
    const float* pts = (const float*)d_in[1];   // (N, 3)
    const float* R   = (const float*)d_in[2];   // (3, 3)
    const float* T   = (const float*)d_in[3];   // (3,)
    float* out = (float*)d_out;                  // (1, N, 128)

    int n = in_sizes[1] / 3;

    init_minmax_kernel<<<1, 1>>>();
    transform_kernel<<<(n + 255) / 256, 256>>>(pts, R, T, n);
    transpose_kernel<<<dim3(NPIX / 32, C_CH / 32), dim3(32, 8)>>>(img);

    // 8 warps per block -> 8 points per block
    int blocks = (n + 7) / 8;
    gather_kernel<<<blocks, 256>>>(out, n);
}

// round 4
// speedup vs baseline: 1.0366x; 1.0366x over previous
#include <cuda_runtime.h>
#include <cfloat>

// Fixed problem shape: img_features (1, 128, 224, 224) fp32, points (N,3), N<=1M.
#define C_CH   128
#define IMG    224
#define NPIX   (IMG * IMG)          // 50176
#define MAXPTS (1 << 20)

// Scratch (static device globals — no allocation at runtime).
__device__ float2 g_xy[MAXPTS];                 // transformed (x,y) per point, 8 MB
__device__ float  g_fmapT[NPIX * C_CH];         // feature map transposed to (x,y,c), 25.7 MB
__device__ int4   g_off[MAXPTS];                // per-point float4-granular gather offsets
__device__ float4 g_w[MAXPTS];                  // per-point bilinear weights (w11,w21,w12,w22)
__device__ int    g_minx, g_maxx, g_miny, g_maxy;   // ordered-int encoded float min/max

// Monotonic float<->int encoding for atomic min/max on floats.
__device__ __forceinline__ int f2oi(float f) {
    int i = __float_as_int(f);
    return (i >= 0) ? i : (i ^ 0x7fffffff);
}
__device__ __forceinline__ float oi2f(int i) {
    return __int_as_float((i >= 0) ? i : (i ^ 0x7fffffff));
}

__global__ void init_minmax_kernel() {
    g_minx = 0x7fffffff;            // +inf ordered
    g_miny = 0x7fffffff;
    g_maxx = 0x80000000;            // -inf ordered
    g_maxy = 0x80000000;
}

// Pass 1: p = points @ R + T (x,y only), stash, and global min/max reduce.
// Rounding pinned to XLA's loop emitter (NO fp contraction):
//   x = ((rn(p0*r0) + rn(p1*r3)) + rn(p2*r6)) + T   — every op individually rounded.
__global__ void transform_kernel(const float* __restrict__ pts,
                                 const float* __restrict__ Rm,
                                 const float* __restrict__ Tv,
                                 int n) {
    int i = blockIdx.x * blockDim.x + threadIdx.x;

    float lminx =  FLT_MAX, lmaxx = -FLT_MAX;
    float lminy =  FLT_MAX, lmaxy = -FLT_MAX;

    if (i < n) {
        float p0 = pts[3 * i + 0];
        float p1 = pts[3 * i + 1];
        float p2 = pts[3 * i + 2];
        float x = __fadd_rn(
                      __fadd_rn(
                          __fadd_rn(__fmul_rn(p0, Rm[0]), __fmul_rn(p1, Rm[3])),
                          __fmul_rn(p2, Rm[6])),
                      Tv[0]);
        float y = __fadd_rn(
                      __fadd_rn(
                          __fadd_rn(__fmul_rn(p0, Rm[1]), __fmul_rn(p1, Rm[4])),
                          __fmul_rn(p2, Rm[7])),
                      Tv[1]);
        g_xy[i] = make_float2(x, y);
        lminx = x; lmaxx = x;
        lminy = y; lmaxy = y;
    }

    // warp reduce
    #pragma unroll
    for (int o = 16; o > 0; o >>= 1) {
        lminx = fminf(lminx, __shfl_xor_sync(0xffffffffu, lminx, o));
        lmaxx = fmaxf(lmaxx, __shfl_xor_sync(0xffffffffu, lmaxx, o));
        lminy = fminf(lminy, __shfl_xor_sync(0xffffffffu, lminy, o));
        lmaxy = fmaxf(lmaxy, __shfl_xor_sync(0xffffffffu, lmaxy, o));
    }

    __shared__ float s0[8], s1[8], s2[8], s3[8];
    int wid  = threadIdx.x >> 5;
    int lane = threadIdx.x & 31;
    if (lane == 0) { s0[wid] = lminx; s1[wid] = lmaxx; s2[wid] = lminy; s3[wid] = lmaxy; }
    __syncthreads();

    if (threadIdx.x == 0) {
        float a = s0[0], b = s1[0], c = s2[0], d = s3[0];
        #pragma unroll
        for (int k = 1; k < 8; k++) {
            a = fminf(a, s0[k]); b = fmaxf(b, s1[k]);
            c = fminf(c, s2[k]); d = fmaxf(d, s3[k]);
        }
        atomicMin(&g_minx, f2oi(a));
        atomicMax(&g_maxx, f2oi(b));
        atomicMin(&g_miny, f2oi(c));
        atomicMax(&g_maxy, f2oi(d));
    }
}

// Pass 2: transpose feature map (C, P) -> (P, C) with P = x*224 + y.
__global__ void transpose_kernel(const float* __restrict__ A) {
    __shared__ float tile[32][33];
    int p0 = blockIdx.x * 32;
    int c0 = blockIdx.y * 32;

    #pragma unroll
    for (int dy = 0; dy < 32; dy += 8)
        tile[threadIdx.y + dy][threadIdx.x] =
            A[(size_t)(c0 + threadIdx.y + dy) * NPIX + (p0 + threadIdx.x)];
    __syncthreads();

    #pragma unroll
    for (int dy = 0; dy < 32; dy += 8)
        g_fmapT[(size_t)(p0 + threadIdx.y + dy) * C_CH + (c0 + threadIdx.x)] =
            tile[threadIdx.x][threadIdx.y + dy];
}

// Pass 3: per-point setup, one thread per point. All rounding pinned (identical
// to the previously bit-exact in-gather computation).
__global__ void prep_kernel(int n) {
    int i = blockIdx.x * blockDim.x + threadIdx.x;
    if (i >= n) return;

    float minx = oi2f(g_minx), maxx = oi2f(g_maxx);
    float miny = oi2f(g_miny), maxy = oi2f(g_maxy);
    // IEEE division — approximate-reciprocal divide flips floor/ceil bins.
    float sx = __fdiv_rn(223.99f, __fsub_rn(maxx, minx));
    float sy = __fdiv_rn(223.99f, __fsub_rn(maxy, miny));

    float2 xy = g_xy[i];
    float xv = __fmul_rn(__fsub_rn(xy.x, minx), sx);
    float yv = __fmul_rn(__fsub_rn(xy.y, miny), sy);

    int x1 = (int)floorf(xv);
    int x2 = min((int)ceilf(xv), IMG - 1);
    int y1 = (int)floorf(yv);
    int y2 = min((int)ceilf(yv), IMG - 1);

    float x1f = (float)x1, x2f = (float)x2;
    float y1f = (float)y1, y2f = (float)y2;
    float4 w;
    w.x = __fmul_rn(__fsub_rn(x2f, xv), __fsub_rn(y2f, yv));  // w11
    w.y = __fmul_rn(__fsub_rn(xv, x1f), __fsub_rn(y2f, yv));  // w21
    w.z = __fmul_rn(__fsub_rn(x2f, xv), __fsub_rn(yv, y1f));  // w12
    w.w = __fmul_rn(__fsub_rn(xv, x1f), __fsub_rn(yv, y1f));  // w22

    int r1 = x1 * IMG, r2 = x2 * IMG;
    int4 off;
    off.x = (r1 + y1) * 32;   // Q11
    off.y = (r2 + y1) * 32;   // Q21
    off.z = (r1 + y2) * 32;   // Q12
    off.w = (r2 + y2) * 32;   // Q22
    g_off[i] = off;
    g_w[i]   = w;
}

// Pass 4: one warp per point; lane handles 4 channels via float4.
// Per-point setup is two broadcast loads; the rest is pure gather + combine.
__global__ void gather_kernel(float* __restrict__ out, int n) {
    int gtid = blockIdx.x * blockDim.x + threadIdx.x;
    int pi   = gtid >> 5;
    int lane = gtid & 31;
    if (pi >= n) return;

    int4   off = g_off[pi];   // uniform across warp -> broadcast
    float4 w   = g_w[pi];

    const float4* __restrict__ f = (const float4*)g_fmapT;
    float4 q11 = f[off.x + lane];
    float4 q21 = f[off.y + lane];
    float4 q12 = f[off.z + lane];
    float4 q22 = f[off.w + lane];

    // reference order, no contraction: ((Q11*w11 + Q21*w21) + Q12*w12) + Q22*w22
    float4 o;
    o.x = __fadd_rn(__fadd_rn(__fadd_rn(__fmul_rn(q11.x, w.x), __fmul_rn(q21.x, w.y)),
                              __fmul_rn(q12.x, w.z)), __fmul_rn(q22.x, w.w));
    o.y = __fadd_rn(__fadd_rn(__fadd_rn(__fmul_rn(q11.y, w.x), __fmul_rn(q21.y, w.y)),
                              __fmul_rn(q12.y, w.z)), __fmul_rn(q22.y, w.w));
    o.z = __fadd_rn(__fadd_rn(__fadd_rn(__fmul_rn(q11.z, w.x), __fmul_rn(q21.z, w.y)),
                              __fmul_rn(q12.z, w.z)), __fmul_rn(q22.z, w.w));
    o.w = __fadd_rn(__fadd_rn(__fadd_rn(__fmul_rn(q11.w, w.x), __fmul_rn(q21.w, w.y)),
                              __fmul_rn(q12.w, w.z)), __fmul_rn(q22.w, w.w));

    ((float4*)out)[(size_t)pi * 32 + lane] = o;
}

extern "C" void kernel_launch(void* const* d_in, const int* in_sizes, int n_in,
                              void* d_out, int out_size) {
    const float* img = (const float*)d_in[0];   // (1, 128, 224, 224)
    const float* pts = (const float*)d_in[1];   // (N, 3)
    const float* R   = (const float*)d_in[2];   // (3, 3)
    const float* T   = (const float*)d_in[3];   // (3,)
    float* out = (float*)d_out;                  // (1, N, 128)

    int n = in_sizes[1] / 3;

    init_minmax_kernel<<<1, 1>>>();
    transform_kernel<<<(n + 255) / 256, 256>>>(pts, R, T, n);
    transpose_kernel<<<dim3(NPIX / 32, C_CH / 32), dim3(32, 8)>>>(img);
    prep_kernel<<<(n + 255) / 256, 256>>>(n);

    // 8 warps per block -> 8 points per block
    int blocks = (n + 7) / 8;
    gather_kernel<<<blocks, 256>>>(out, n);
}